// round 1
// baseline (speedup 1.0000x reference)
#include <cuda_runtime.h>
#include <math.h>

// Problem constants
#define BB   16
#define CI   64
#define CO   64
#define SS   256
#define MM1  32
#define MM2  32
#define NR   63            // 2*m1-1 fx modes (fx = r-31)
#define NMODE (NR*MM2)     // 2016
#define NBI  (BB*CI)       // 1024
#define NBO  (BB*CO)       // 1024
#define KKC  64            // 2*MM2 interleaved re/im columns

// -------- device scratch (allowed: __device__ globals, no allocs) --------
__device__ float g_tab[512];                    // cos[0..255], sin[256..511]
__device__ float g_TP[(size_t)NBI * SS * KKC];  // stage1 out T, later reused as stage4 out P (67MB)
__device__ float g_M1[(size_t)NBI * NMODE * 2]; // [bi][mode][2]
__device__ float g_W [(size_t)NMODE * CI * CO * 2]; // [mode][i*64+o][2] (scaled)
__device__ float g_M2[(size_t)NMODE * NBO * 2]; // [mode][b*64+o][2]

// ======================= K0: trig table =======================
__global__ void k_tab() {
    int n = threadIdx.x;
    double a = 2.0 * M_PI * (double)n / 256.0;
    g_tab[n]       = (float)cos(a);
    g_tab[256 + n] = (float)sin(a);
}

// ======================= K1: weight build + transpose =======================
// Build W[mode][io] from y0/yposx/w00 with fftshift row logic, conj-flip, and
// folded scale: w_ky (1 for ky=0 else 2) / 65536 (ortho fwd*inv).
__global__ void k_wbuild(const float* __restrict__ y0r, const float* __restrict__ y0i,
                         const float* __restrict__ ypr, const float* __restrict__ ypi,
                         const float* __restrict__ w00) {
    __shared__ float2 tile[32][33];
    int m0 = blockIdx.x * 32, io0 = blockIdx.y * 32;
    int tx = threadIdx.x, ty = threadIdx.y;   // 32 x 8
    #pragma unroll
    for (int q = 0; q < 4; q++) {
        int io = io0 + ty + 8 * q;
        int m  = m0 + tx;
        int r = m >> 5, k = m & 31;
        float wr, wi;
        if (k == 0) {
            if (r < 31)       { wr = y0r[io * 31 + r];        wi =  y0i[io * 31 + r]; }
            else if (r == 31) { wr = w00[io];                 wi =  0.f; }
            else              { wr = y0r[io * 31 + (62 - r)]; wi = -y0i[io * 31 + (62 - r)]; }
        } else {
            int idx = (io * 63 + r) * 31 + (k - 1);
            wr = ypr[idx]; wi = ypi[idx];
        }
        float sc = (k == 0 ? 1.0f : 2.0f) * (1.0f / 65536.0f);
        tile[ty + 8 * q][tx] = make_float2(wr * sc, wi * sc);
    }
    __syncthreads();
    #pragma unroll
    for (int q = 0; q < 4; q++) {
        int m  = m0 + ty + 8 * q;
        int io = io0 + tx;
        float2 w = tile[tx][ty + 8 * q];
        ((float2*)g_W)[(size_t)m * 4096 + io] = w;
    }
}

// ======================= K2: stage1 column DFT (GEMM 262144x64x256) =======================
// T[bi][u][2ky]   = sum_v x[bi][u][v] * cos(2pi ky v/256)
// T[bi][u][2ky+1] = sum_v x[bi][u][v] * -sin(2pi ky v/256)
__global__ void __launch_bounds__(256) k_s1(const float* __restrict__ x) {
    extern __shared__ float sm[];
    float* As = sm;                 // [32][257] transposed A tile
    float* Es = sm + 32 * 257;      // [256][64]
    // build E from trig table
    for (int idx = threadIdx.x; idx < 256 * 64; idx += 256) {
        int v = idx >> 6, kk = idx & 63, ky = kk >> 1;
        int a = (ky * v) & 255;
        Es[idx] = (kk & 1) ? -g_tab[256 + a] : g_tab[a];
    }
    int row0 = blockIdx.x * 256;
    int i = threadIdx.x & 31, j = threadIdx.x >> 5;  // i:row lane, j:col group 0..7
    float acc[8][8];
    #pragma unroll
    for (int t = 0; t < 8; t++)
        #pragma unroll
        for (int s2 = 0; s2 < 8; s2++) acc[t][s2] = 0.f;

    for (int k0 = 0; k0 < 256; k0 += 32) {
        __syncthreads();
        const float4* src = (const float4*)(x + (size_t)(row0 + threadIdx.x) * 256 + k0);
        #pragma unroll
        for (int q = 0; q < 8; q++) {
            float4 v4 = src[q];
            As[(q * 4 + 0) * 257 + threadIdx.x] = v4.x;
            As[(q * 4 + 1) * 257 + threadIdx.x] = v4.y;
            As[(q * 4 + 2) * 257 + threadIdx.x] = v4.z;
            As[(q * 4 + 3) * 257 + threadIdx.x] = v4.w;
        }
        __syncthreads();
        #pragma unroll 4
        for (int k = 0; k < 32; k++) {
            float a[8], b[8];
            #pragma unroll
            for (int t = 0; t < 8; t++) a[t] = As[k * 257 + i + 32 * t];
            #pragma unroll
            for (int s2 = 0; s2 < 8; s2++) b[s2] = Es[(k0 + k) * 64 + j + 8 * s2];
            #pragma unroll
            for (int t = 0; t < 8; t++)
                #pragma unroll
                for (int s2 = 0; s2 < 8; s2++) acc[t][s2] += a[t] * b[s2];
        }
    }
    // epilogue via smem for coalesced stores (sC overlaps As/Es, both dead now)
    __syncthreads();
    float* sC = sm;  // [256][65]
    #pragma unroll
    for (int t = 0; t < 8; t++)
        #pragma unroll
        for (int s2 = 0; s2 < 8; s2++)
            sC[(i + 32 * t) * 65 + j + 8 * s2] = acc[t][s2];
    __syncthreads();
    for (int f = threadIdx.x; f < 256 * 16; f += 256) {
        int r = f >> 4, c4 = (f & 15) * 4;
        float4 v4 = make_float4(sC[r * 65 + c4], sC[r * 65 + c4 + 1],
                                sC[r * 65 + c4 + 2], sC[r * 65 + c4 + 3]);
        ((float4*)(g_TP + (size_t)(row0 + r) * 64))[f & 15] = v4;
    }
}

// ======================= K3: stage2 row DFT per image =======================
// M1[bi][r*32+ky] = sum_u e^{-2pi i (r-31) u /256} * T[bi][u][ky]
__global__ void __launch_bounds__(128) k_s2() {
    extern __shared__ float sm[];
    float* Ts = sm;            // [256][64] interleaved re/im
    float* st = sm + 256 * 64; // [512] trig
    int bi = blockIdx.x;
    for (int idx = threadIdx.x; idx < 512; idx += 128) st[idx] = g_tab[idx];
    {
        const float4* src = (const float4*)(g_TP + (size_t)bi * SS * KKC);
        for (int idx = threadIdx.x; idx < 256 * 16; idx += 128)
            ((float4*)Ts)[idx] = src[idx];
    }
    __syncthreads();
    const float2* Ts2 = (const float2*)Ts;
    int fxg = threadIdx.x & 15, kyg = threadIdx.x >> 4;  // 16 x 8
    float aR[4][4], aI[4][4];
    #pragma unroll
    for (int t = 0; t < 4; t++)
        #pragma unroll
        for (int s2 = 0; s2 < 4; s2++) { aR[t][s2] = 0.f; aI[t][s2] = 0.f; }

    #pragma unroll 2
    for (int u = 0; u < 256; u++) {
        float tr[4], ti[4], c[4], sn[4];
        #pragma unroll
        for (int s2 = 0; s2 < 4; s2++) {
            float2 tv = Ts2[u * 32 + kyg + 8 * s2];
            tr[s2] = tv.x; ti[s2] = tv.y;
        }
        #pragma unroll
        for (int t = 0; t < 4; t++) {
            int r = fxg + 16 * t;          // r=63 computed, discarded
            int idx = ((r - 31) * u) & 255;
            c[t] = st[idx]; sn[t] = st[256 + idx];
        }
        #pragma unroll
        for (int t = 0; t < 4; t++)
            #pragma unroll
            for (int s2 = 0; s2 < 4; s2++) {
                aR[t][s2] += tr[s2] * c[t] + ti[s2] * sn[t];
                aI[t][s2] += ti[s2] * c[t] - tr[s2] * sn[t];
            }
    }
    float2* out = (float2*)(g_M1 + (size_t)bi * NMODE * 2);
    #pragma unroll
    for (int t = 0; t < 4; t++) {
        int r = fxg + 16 * t;
        if (r < 63) {
            #pragma unroll
            for (int s2 = 0; s2 < 4; s2++) {
                int ky = kyg + 8 * s2;
                out[r * 32 + ky] = make_float2(aR[t][s2], aI[t][s2]);
            }
        }
    }
}

// ======================= K4: stage3 channel mix per mode =======================
// M2[m][b][o] = sum_i M1[b][i][m] * W[m][i][o]   (complex)
__global__ void __launch_bounds__(256) k_s3() {
    __shared__ float2 Ws[4096];
    __shared__ float2 Ms[1024];
    int m = blockIdx.x;
    {
        const float2* wsrc = (const float2*)g_W + (size_t)m * 4096;
        for (int idx = threadIdx.x; idx < 4096; idx += 256) Ws[idx] = wsrc[idx];
        const float2* msrc = (const float2*)g_M1;
        for (int idx = threadIdx.x; idx < 1024; idx += 256)
            Ms[idx] = msrc[(size_t)idx * NMODE + m];
    }
    __syncthreads();
    int o = threadIdx.x & 63, bg = threadIdx.x >> 6;  // bg 0..3
    float oR[4], oI[4];
    #pragma unroll
    for (int t = 0; t < 4; t++) { oR[t] = 0.f; oI[t] = 0.f; }
    for (int ii = 0; ii < 64; ii++) {
        float2 w = Ws[ii * 64 + o];
        #pragma unroll
        for (int t = 0; t < 4; t++) {
            float2 mm = Ms[(bg + 4 * t) * 64 + ii];
            oR[t] += mm.x * w.x - mm.y * w.y;
            oI[t] += mm.x * w.y + mm.y * w.x;
        }
    }
    float2* out = (float2*)g_M2 + (size_t)m * 1024;
    #pragma unroll
    for (int t = 0; t < 4; t++)
        out[(bg + 4 * t) * 64 + o] = make_float2(oR[t], oI[t]);
}

// ======================= K5: stage4 inverse row DFT per (b,o) =======================
// P[bo][s][ky] = sum_r M2[r*32+ky][bo] * e^{+2pi i (r-31) s/256}
__global__ void __launch_bounds__(512) k_s4() {
    __shared__ float2 Ms[NMODE];
    __shared__ float st[512];
    int bo = blockIdx.x;
    for (int idx = threadIdx.x; idx < 512; idx += 512) st[idx] = g_tab[idx];
    {
        const float2* msrc = (const float2*)g_M2;
        for (int idx = threadIdx.x; idx < NMODE; idx += 512)
            Ms[idx] = msrc[(size_t)idx * 1024 + bo];
    }
    __syncthreads();
    int kyg = threadIdx.x & 7, sg = threadIdx.x >> 3;  // sg 0..63
    float pR[4][4], pI[4][4];
    #pragma unroll
    for (int t = 0; t < 4; t++)
        #pragma unroll
        for (int u = 0; u < 4; u++) { pR[t][u] = 0.f; pI[t][u] = 0.f; }

    for (int r = 0; r < 63; r++) {
        int fx = r - 31;
        float c[4], sn[4], mr[4], mi[4];
        #pragma unroll
        for (int t = 0; t < 4; t++) {
            int s2 = sg + 64 * t;
            int idx = (fx * s2) & 255;
            c[t] = st[idx]; sn[t] = st[256 + idx];
        }
        #pragma unroll
        for (int u = 0; u < 4; u++) {
            float2 mm = Ms[r * 32 + kyg + 8 * u];
            mr[u] = mm.x; mi[u] = mm.y;
        }
        #pragma unroll
        for (int t = 0; t < 4; t++)
            #pragma unroll
            for (int u = 0; u < 4; u++) {
                pR[t][u] += mr[u] * c[t] - mi[u] * sn[t];
                pI[t][u] += mr[u] * sn[t] + mi[u] * c[t];
            }
    }
    float2* out = (float2*)(g_TP + (size_t)bo * SS * KKC);  // reuse T buffer as P
    #pragma unroll
    for (int t = 0; t < 4; t++)
        #pragma unroll
        for (int u = 0; u < 4; u++)
            out[(sg + 64 * t) * 32 + kyg + 8 * u] = make_float2(pR[t][u], pI[t][u]);
}

// ======================= K6: stage5 inverse column (GEMM 262144x256x64) =======================
// y[bo][s][t] = sum_ky Pr[s][ky]*cos(2pi ky t/256) - Pi[s][ky]*sin(2pi ky t/256)
__global__ void __launch_bounds__(256) k_s5(float* __restrict__ y) {
    extern __shared__ float sm[];
    float* As = sm;                  // [64][65] transposed P tile
    float* Bs = sm + 64 * 65;        // [64][256]
    for (int idx = threadIdx.x; idx < 64 * 256; idx += 256) {
        int kk = idx >> 8, t = idx & 255, ky = kk >> 1;
        int a = (ky * t) & 255;
        Bs[idx] = (kk & 1) ? -g_tab[256 + a] : g_tab[a];
    }
    int row0 = blockIdx.x * 64;
    {
        const float4* src = (const float4*)(g_TP + (size_t)row0 * 64);
        for (int f = threadIdx.x; f < 1024; f += 256) {
            float4 v4 = src[f];
            int r = f >> 4, c4 = (f & 15) * 4;
            As[(c4 + 0) * 65 + r] = v4.x;
            As[(c4 + 1) * 65 + r] = v4.y;
            As[(c4 + 2) * 65 + r] = v4.z;
            As[(c4 + 3) * 65 + r] = v4.w;
        }
    }
    __syncthreads();
    int i = threadIdx.x & 15, j = threadIdx.x >> 4;   // 16 x 16
    float acc[4][16];
    #pragma unroll
    for (int t = 0; t < 4; t++)
        #pragma unroll
        for (int s2 = 0; s2 < 16; s2++) acc[t][s2] = 0.f;
    #pragma unroll 2
    for (int k = 0; k < 64; k++) {
        float a[4], b[16];
        #pragma unroll
        for (int t = 0; t < 4; t++) a[t] = As[k * 65 + i + 16 * t];
        #pragma unroll
        for (int s2 = 0; s2 < 16; s2++) b[s2] = Bs[k * 256 + j + 16 * s2];
        #pragma unroll
        for (int t = 0; t < 4; t++)
            #pragma unroll
            for (int s2 = 0; s2 < 16; s2++) acc[t][s2] += a[t] * b[s2];
    }
    __syncthreads();
    float* sC = sm;  // [64][257] overlaps As/Bs (dead)
    #pragma unroll
    for (int t = 0; t < 4; t++)
        #pragma unroll
        for (int s2 = 0; s2 < 16; s2++)
            sC[(i + 16 * t) * 257 + j + 16 * s2] = acc[t][s2];
    __syncthreads();
    for (int f = threadIdx.x; f < 64 * 64; f += 256) {
        int r = f >> 6, c4 = (f & 63) * 4;
        float4 v4 = make_float4(sC[r * 257 + c4], sC[r * 257 + c4 + 1],
                                sC[r * 257 + c4 + 2], sC[r * 257 + c4 + 3]);
        ((float4*)(y + (size_t)(row0 + r) * 256))[f & 63] = v4;
    }
}

// ======================= launcher =======================
extern "C" void kernel_launch(void* const* d_in, const int* in_sizes, int n_in,
                              void* d_out, int out_size) {
    const float* x   = (const float*)d_in[0];
    const float* y0r = (const float*)d_in[1];
    const float* y0i = (const float*)d_in[2];
    const float* ypr = (const float*)d_in[3];
    const float* ypi = (const float*)d_in[4];
    const float* w00 = (const float*)d_in[5];
    float* y = (float*)d_out;

    cudaFuncSetAttribute(k_s1, cudaFuncAttributeMaxDynamicSharedMemorySize, (32 * 257 + 256 * 64) * 4);
    cudaFuncSetAttribute(k_s2, cudaFuncAttributeMaxDynamicSharedMemorySize, (256 * 64 + 512) * 4);
    cudaFuncSetAttribute(k_s5, cudaFuncAttributeMaxDynamicSharedMemorySize, (64 * 65 + 64 * 256) * 4);

    k_tab<<<1, 256>>>();
    k_wbuild<<<dim3(63, 128), dim3(32, 8)>>>(y0r, y0i, ypr, ypi, w00);
    k_s1<<<1024, 256, (32 * 257 + 256 * 64) * 4>>>(x);
    k_s2<<<1024, 128, (256 * 64 + 512) * 4>>>();
    k_s3<<<2016, 256>>>();
    k_s4<<<1024, 512>>>();
    k_s5<<<4096, 256, (64 * 65 + 64 * 256) * 4>>>(y);
}

// round 3
// speedup vs baseline: 1.1957x; 1.1957x over previous
#include <cuda_runtime.h>
#include <math.h>

// Problem constants
#define BB   16
#define CI   64
#define CO   64
#define SS   256
#define MM1  32
#define MM2  32
#define NR   63            // 2*m1-1 fx modes (fx = r-31)
#define NMODE (NR*MM2)     // 2016
#define NBI  (BB*CI)       // 1024
#define NBO  (BB*CO)       // 1024
#define KKC  64            // 2*MM2 interleaved re/im columns

typedef unsigned long long u64t;

// ---- packed f32x2 helpers (FFMA2 path, Blackwell-only via PTX) ----
__device__ __forceinline__ u64t pk(float lo, float hi) {
    u64t r;
    asm("mov.b64 %0, {%1, %2};" : "=l"(r)
        : "r"(__float_as_uint(lo)), "r"(__float_as_uint(hi)));
    return r;
}
__device__ __forceinline__ u64t pk2(float v) { return pk(v, v); }
__device__ __forceinline__ float2 upk(u64t v) {
    unsigned lo, hi;
    asm("mov.b64 {%0, %1}, %2;" : "=r"(lo), "=r"(hi) : "l"(v));
    return make_float2(__uint_as_float(lo), __uint_as_float(hi));
}
__device__ __forceinline__ void fma2(u64t& d, u64t a, u64t b) {
    asm("fma.rn.f32x2 %0, %1, %2, %3;" : "=l"(d) : "l"(a), "l"(b), "l"(d));
}

// -------- device scratch (allowed: __device__ globals, no allocs) --------
__device__ float g_tab[512];                    // cos[0..255], sin[256..511]
__device__ float g_TP[(size_t)NBI * SS * KKC];  // stage1 out T, later reused as stage4 out P (67MB)
__device__ float g_M1[(size_t)NBI * NMODE * 2]; // [bi][mode][2]
__device__ float g_W [(size_t)NMODE * CI * CO * 2]; // [mode][i*64+o][2] (scaled)
__device__ float g_M2[(size_t)NMODE * NBO * 2]; // [mode][b*64+o][2]

// ======================= K0: trig table =======================
__global__ void k_tab() {
    int n = threadIdx.x;
    double a = 2.0 * M_PI * (double)n / 256.0;
    g_tab[n]       = (float)cos(a);
    g_tab[256 + n] = (float)sin(a);
}

// ======================= K1: weight build + transpose =======================
__global__ void k_wbuild(const float* __restrict__ y0r, const float* __restrict__ y0i,
                         const float* __restrict__ ypr, const float* __restrict__ ypi,
                         const float* __restrict__ w00) {
    __shared__ float2 tile[32][33];
    int m0 = blockIdx.x * 32, io0 = blockIdx.y * 32;
    int tx = threadIdx.x, ty = threadIdx.y;   // 32 x 8
    #pragma unroll
    for (int q = 0; q < 4; q++) {
        int io = io0 + ty + 8 * q;
        int m  = m0 + tx;
        int r = m >> 5, k = m & 31;
        float wr, wi;
        if (k == 0) {
            if (r < 31)       { wr = y0r[io * 31 + r];        wi =  y0i[io * 31 + r]; }
            else if (r == 31) { wr = w00[io];                 wi =  0.f; }
            else              { wr = y0r[io * 31 + (62 - r)]; wi = -y0i[io * 31 + (62 - r)]; }
        } else {
            int idx = (io * 63 + r) * 31 + (k - 1);
            wr = ypr[idx]; wi = ypi[idx];
        }
        float sc = (k == 0 ? 1.0f : 2.0f) * (1.0f / 65536.0f);
        tile[ty + 8 * q][tx] = make_float2(wr * sc, wi * sc);
    }
    __syncthreads();
    #pragma unroll
    for (int q = 0; q < 4; q++) {
        int m  = m0 + ty + 8 * q;
        int io = io0 + tx;
        float2 w = tile[tx][ty + 8 * q];
        ((float2*)g_W)[(size_t)m * 4096 + io] = w;
    }
}

// ======================= K2: stage1 column DFT (GEMM 262144x64x256) =======================
__global__ void __launch_bounds__(256) k_s1(const float* __restrict__ x) {
    extern __shared__ float sm[];
    float* As = sm;                 // [32][257] transposed A tile
    float* Es = sm + 32 * 257;      // [256][64]  (byte offset %8 == 0)
    for (int idx = threadIdx.x; idx < 256 * 64; idx += 256) {
        int v = idx >> 6, kk = idx & 63, ky = kk >> 1;
        int a = (ky * v) & 255;
        Es[idx] = (kk & 1) ? -g_tab[256 + a] : g_tab[a];
    }
    int row0 = blockIdx.x * 256;
    int i = threadIdx.x & 31, j = threadIdx.x >> 5;  // i:row lane(32), j:pair group(8)
    u64t acc2[8][4];
    #pragma unroll
    for (int t = 0; t < 8; t++)
        #pragma unroll
        for (int p = 0; p < 4; p++) acc2[t][p] = 0ULL;

    for (int k0 = 0; k0 < 256; k0 += 32) {
        __syncthreads();
        const float4* src = (const float4*)(x + (size_t)(row0 + threadIdx.x) * 256 + k0);
        #pragma unroll
        for (int q = 0; q < 8; q++) {
            float4 v4 = src[q];
            As[(q * 4 + 0) * 257 + threadIdx.x] = v4.x;
            As[(q * 4 + 1) * 257 + threadIdx.x] = v4.y;
            As[(q * 4 + 2) * 257 + threadIdx.x] = v4.z;
            As[(q * 4 + 3) * 257 + threadIdx.x] = v4.w;
        }
        __syncthreads();
        #pragma unroll 4
        for (int k = 0; k < 32; k++) {
            u64t a2[8], b2[4];
            #pragma unroll
            for (int t = 0; t < 8; t++) a2[t] = pk2(As[k * 257 + i + 32 * t]);
            #pragma unroll
            for (int p = 0; p < 4; p++)
                b2[p] = *(const u64t*)&Es[(k0 + k) * 64 + 2 * (j + 8 * p)];
            #pragma unroll
            for (int t = 0; t < 8; t++)
                #pragma unroll
                for (int p = 0; p < 4; p++) fma2(acc2[t][p], a2[t], b2[p]);
        }
    }
    __syncthreads();
    float* sC = sm;  // [256][65]
    #pragma unroll
    for (int t = 0; t < 8; t++)
        #pragma unroll
        for (int p = 0; p < 4; p++) {
            float2 up = upk(acc2[t][p]);
            int c = 2 * (j + 8 * p);
            sC[(i + 32 * t) * 65 + c]     = up.x;
            sC[(i + 32 * t) * 65 + c + 1] = up.y;
        }
    __syncthreads();
    for (int f = threadIdx.x; f < 256 * 16; f += 256) {
        int r = f >> 4, c4 = (f & 15) * 4;
        float4 v4 = make_float4(sC[r * 65 + c4], sC[r * 65 + c4 + 1],
                                sC[r * 65 + c4 + 2], sC[r * 65 + c4 + 3]);
        ((float4*)(g_TP + (size_t)(row0 + r) * 64))[f & 15] = v4;
    }
}

// ======================= K3: stage2 row DFT per image =======================
// M1[bi][r*32+ky] = sum_u e^{-2pi i (r-31) u /256} * T[bi][u][ky]
__global__ void __launch_bounds__(128) k_s2() {
    extern __shared__ float sm[];
    float* Ts = sm;            // [256][64] interleaved re/im
    float* st = sm + 256 * 64; // [512] trig
    int bi = blockIdx.x;
    for (int idx = threadIdx.x; idx < 512; idx += 128) st[idx] = g_tab[idx];
    {
        const float4* src = (const float4*)(g_TP + (size_t)bi * SS * KKC);
        for (int idx = threadIdx.x; idx < 256 * 16; idx += 128)
            ((float4*)Ts)[idx] = src[idx];
    }
    __syncthreads();
    int fxg = threadIdx.x & 15, kyg = threadIdx.x >> 4;  // 16 x 8
    u64t acc2[4][4];   // {aR, aI}
    #pragma unroll
    for (int t = 0; t < 4; t++)
        #pragma unroll
        for (int s2 = 0; s2 < 4; s2++) acc2[t][s2] = 0ULL;

    #pragma unroll 2
    for (int u = 0; u < 256; u++) {
        u64t tv[4], tw[4], c2[4], s2v[4];
        #pragma unroll
        for (int s2 = 0; s2 < 4; s2++) {
            tv[s2] = *(const u64t*)&Ts[(u * 32 + kyg + 8 * s2) * 2];
            float2 f = upk(tv[s2]);
            tw[s2] = pk(f.y, -f.x);          // {ti, -tr}
        }
        #pragma unroll
        for (int t = 0; t < 4; t++) {
            int r = fxg + 16 * t;
            int idx = ((r - 31) * u) & 255;
            c2[t]  = pk2(st[idx]);
            s2v[t] = pk2(st[256 + idx]);
        }
        #pragma unroll
        for (int t = 0; t < 4; t++)
            #pragma unroll
            for (int s2 = 0; s2 < 4; s2++) {
                fma2(acc2[t][s2], tv[s2], c2[t]);   // aR+=tr*c,  aI+=ti*c
                fma2(acc2[t][s2], tw[s2], s2v[t]);  // aR+=ti*sn, aI-=tr*sn
            }
    }
    float2* out = (float2*)(g_M1 + (size_t)bi * NMODE * 2);
    #pragma unroll
    for (int t = 0; t < 4; t++) {
        int r = fxg + 16 * t;
        if (r < 63) {
            #pragma unroll
            for (int s2 = 0; s2 < 4; s2++) {
                int ky = kyg + 8 * s2;
                float2 up = upk(acc2[t][s2]);
                out[r * 32 + ky] = make_float2(up.x, up.y);
            }
        }
    }
}

// ======================= K4: stage3 channel mix per mode =======================
// M2[m][b][o] = sum_i M1[b][i][m] * W[m][i][o]   (complex)
__global__ void __launch_bounds__(128) k_s3() {
    __shared__ float2 Ws[4096];
    __shared__ float2 Ms[1024];
    int m = blockIdx.x;
    {
        const float2* wsrc = (const float2*)g_W + (size_t)m * 4096;
        for (int idx = threadIdx.x; idx < 4096; idx += 128) Ws[idx] = wsrc[idx];
        const float2* msrc = (const float2*)g_M1;
        for (int idx = threadIdx.x; idx < 1024; idx += 128)
            Ms[idx] = msrc[(size_t)idx * NMODE + m];
    }
    __syncthreads();
    int o2 = threadIdx.x & 31, bg = threadIdx.x >> 5;  // o pair lane(32) x bg(4)
    u64t acc2[2][4];   // {oR, oI} for 2 o x 4 b
    #pragma unroll
    for (int oo = 0; oo < 2; oo++)
        #pragma unroll
        for (int t = 0; t < 4; t++) acc2[oo][t] = 0ULL;
    for (int ii = 0; ii < 64; ii++) {
        float2 wa = Ws[ii * 64 + 2 * o2];
        float2 wb = Ws[ii * 64 + 2 * o2 + 1];
        u64t waP = pk(wa.x, wa.y), waN = pk(-wa.y, wa.x);
        u64t wbP = pk(wb.x, wb.y), wbN = pk(-wb.y, wb.x);
        #pragma unroll
        for (int t = 0; t < 4; t++) {
            float2 mm = Ms[(bg + 4 * t) * 64 + ii];
            u64t mdx = pk2(mm.x), mdy = pk2(mm.y);
            fma2(acc2[0][t], mdx, waP); fma2(acc2[0][t], mdy, waN);
            fma2(acc2[1][t], mdx, wbP); fma2(acc2[1][t], mdy, wbN);
        }
    }
    float2* out = (float2*)g_M2 + (size_t)m * 1024;
    #pragma unroll
    for (int t = 0; t < 4; t++)
        #pragma unroll
        for (int oo = 0; oo < 2; oo++) {
            float2 up = upk(acc2[oo][t]);
            out[(bg + 4 * t) * 64 + 2 * o2 + oo] = make_float2(up.x, up.y);
        }
}

// ======================= K5: stage4 inverse row DFT per (b,o) =======================
// P[bo][s][ky] = sum_r M2[r*32+ky][bo] * e^{+2pi i (r-31) s/256}
__global__ void __launch_bounds__(512) k_s4() {
    __shared__ float2 Ms[NMODE];
    __shared__ float st[512];
    int bo = blockIdx.x;
    for (int idx = threadIdx.x; idx < 512; idx += 512) st[idx] = g_tab[idx];
    {
        const float2* msrc = (const float2*)g_M2;
        for (int idx = threadIdx.x; idx < NMODE; idx += 512)
            Ms[idx] = msrc[(size_t)idx * 1024 + bo];
    }
    __syncthreads();
    int kyg = threadIdx.x & 7, sg = threadIdx.x >> 3;  // 8 x 64
    u64t acc2[4][4];   // {pR, pI}
    #pragma unroll
    for (int t = 0; t < 4; t++)
        #pragma unroll
        for (int u = 0; u < 4; u++) acc2[t][u] = 0ULL;

    for (int r = 0; r < 63; r++) {
        int fx = r - 31;
        u64t m2[4], msw[4], c2[4], sp[4];
        #pragma unroll
        for (int u = 0; u < 4; u++) {
            m2[u] = *(const u64t*)&Ms[r * 32 + kyg + 8 * u];
            float2 f = upk(m2[u]);
            msw[u] = pk(f.y, f.x);         // {mi, mr}
        }
        #pragma unroll
        for (int t = 0; t < 4; t++) {
            int s2 = sg + 64 * t;
            int idx = (fx * s2) & 255;
            float sn = st[256 + idx];
            c2[t] = pk2(st[idx]);
            sp[t] = pk(-sn, sn);           // {-sn, sn}
        }
        #pragma unroll
        for (int t = 0; t < 4; t++)
            #pragma unroll
            for (int u = 0; u < 4; u++) {
                fma2(acc2[t][u], c2[t], m2[u]);   // pR+=c*mr,  pI+=c*mi
                fma2(acc2[t][u], sp[t], msw[u]);  // pR-=sn*mi, pI+=sn*mr
            }
    }
    float2* out = (float2*)(g_TP + (size_t)bo * SS * KKC);  // reuse T buffer as P
    #pragma unroll
    for (int t = 0; t < 4; t++)
        #pragma unroll
        for (int u = 0; u < 4; u++) {
            float2 up = upk(acc2[t][u]);
            out[(sg + 64 * t) * 32 + kyg + 8 * u] = make_float2(up.x, up.y);
        }
}

// ======================= K6: stage5 inverse column (GEMM 262144x256x64) =======================
__global__ void __launch_bounds__(256) k_s5(float* __restrict__ y) {
    extern __shared__ float sm[];
    float* As = sm;                  // [64][65] transposed P tile
    float* Bs = sm + 64 * 65;        // [64][256] (byte offset %8 == 0)
    for (int idx = threadIdx.x; idx < 64 * 256; idx += 256) {
        int kk = idx >> 8, t = idx & 255, ky = kk >> 1;
        int a = (ky * t) & 255;
        Bs[idx] = (kk & 1) ? -g_tab[256 + a] : g_tab[a];
    }
    int row0 = blockIdx.x * 64;
    {
        const float4* src = (const float4*)(g_TP + (size_t)row0 * 64);
        for (int f = threadIdx.x; f < 1024; f += 256) {
            float4 v4 = src[f];
            int r = f >> 4, c4 = (f & 15) * 4;
            As[(c4 + 0) * 65 + r] = v4.x;
            As[(c4 + 1) * 65 + r] = v4.y;
            As[(c4 + 2) * 65 + r] = v4.z;
            As[(c4 + 3) * 65 + r] = v4.w;
        }
    }
    __syncthreads();
    int i = threadIdx.x & 15, j = threadIdx.x >> 4;   // 16 x 16
    u64t acc2[4][8];
    #pragma unroll
    for (int t = 0; t < 4; t++)
        #pragma unroll
        for (int p = 0; p < 8; p++) acc2[t][p] = 0ULL;
    #pragma unroll 2
    for (int k = 0; k < 64; k++) {
        u64t a2[4], b2[8];
        #pragma unroll
        for (int t = 0; t < 4; t++) a2[t] = pk2(As[k * 65 + i + 16 * t]);
        #pragma unroll
        for (int p = 0; p < 8; p++)
            b2[p] = *(const u64t*)&Bs[k * 256 + 2 * (j + 16 * p)];
        #pragma unroll
        for (int t = 0; t < 4; t++)
            #pragma unroll
            for (int p = 0; p < 8; p++) fma2(acc2[t][p], a2[t], b2[p]);
    }
    __syncthreads();
    float* sC = sm;  // [64][257]
    #pragma unroll
    for (int t = 0; t < 4; t++)
        #pragma unroll
        for (int p = 0; p < 8; p++) {
            float2 up = upk(acc2[t][p]);
            int c = 2 * (j + 16 * p);
            sC[(i + 16 * t) * 257 + c]     = up.x;
            sC[(i + 16 * t) * 257 + c + 1] = up.y;
        }
    __syncthreads();
    for (int f = threadIdx.x; f < 64 * 64; f += 256) {
        int r = f >> 6, c4 = (f & 63) * 4;
        float4 v4 = make_float4(sC[r * 257 + c4], sC[r * 257 + c4 + 1],
                                sC[r * 257 + c4 + 2], sC[r * 257 + c4 + 3]);
        ((float4*)(y + (size_t)(row0 + r) * 256))[f & 63] = v4;
    }
}

// ======================= launcher =======================
extern "C" void kernel_launch(void* const* d_in, const int* in_sizes, int n_in,
                              void* d_out, int out_size) {
    const float* x   = (const float*)d_in[0];
    const float* y0r = (const float*)d_in[1];
    const float* y0i = (const float*)d_in[2];
    const float* ypr = (const float*)d_in[3];
    const float* ypi = (const float*)d_in[4];
    const float* w00 = (const float*)d_in[5];
    float* y = (float*)d_out;

    cudaFuncSetAttribute(k_s1, cudaFuncAttributeMaxDynamicSharedMemorySize, (32 * 257 + 256 * 64) * 4);
    cudaFuncSetAttribute(k_s2, cudaFuncAttributeMaxDynamicSharedMemorySize, (256 * 64 + 512) * 4);
    cudaFuncSetAttribute(k_s5, cudaFuncAttributeMaxDynamicSharedMemorySize, (64 * 65 + 64 * 256) * 4);

    k_tab<<<1, 256>>>();
    k_wbuild<<<dim3(63, 128), dim3(32, 8)>>>(y0r, y0i, ypr, ypi, w00);
    k_s1<<<1024, 256, (32 * 257 + 256 * 64) * 4>>>(x);
    k_s2<<<1024, 128, (256 * 64 + 512) * 4>>>();
    k_s3<<<2016, 128>>>();
    k_s4<<<1024, 512>>>();
    k_s5<<<4096, 256, (64 * 65 + 64 * 256) * 4>>>(y);
}